// round 3
// baseline (speedup 1.0000x reference)
#include <cuda_runtime.h>

// Problem constants
#define NB 4
#define NL 1024
#define ND 768
#define NH 12
#define NHD 64
#define NSCALE 0.125f   // 64^-0.5

// Scratch (allocation-free rule: static __device__ arrays)
__device__ float g_Q[NB * NH * NL * NHD];
__device__ float g_K[NB * NH * NL * NHD];
__device__ float g_V[NB * NH * NL * NHD];
__device__ float g_O[NB * NL * ND];

// ---------------------------------------------------------------------------
// SGEMM: C[m,n] = sum_k A[m,k] * W[n,k] + bias[n]
// A row-major [M,768], W row-major [N,768] (K-contiguous both) -> "NT" gemm.
// BM=BN=128, BK=8, 256 threads, 8x8 fragment per thread.
// MODE 0: QKV projection epilogue -> scatter into g_Q (scaled) / g_K / g_V
// MODE 1: output projection epilogue -> write d_out
// ---------------------------------------------------------------------------
template <int MODE>
__global__ __launch_bounds__(256)
void sgemm_kernel(const float* __restrict__ A_in,
                  const float* __restrict__ W,
                  const float* __restrict__ bias,
                  float* __restrict__ out)
{
    constexpr int K = 768;
    constexpr int BM = 128, BN = 128, BK = 8;
    __shared__ float As[BK][BM];
    __shared__ float Bs[BK][BN];

    const float* A = (MODE == 1) ? (const float*)g_O : A_in;

    const int tid = threadIdx.x;
    const int tx = tid & 15;        // 0..15  -> N direction
    const int ty = tid >> 4;        // 0..15  -> M direction
    const int m0 = blockIdx.y * BM;
    const int n0 = blockIdx.x * BN;

    // loader mapping: 2 threads per row, float4 each (128 rows x 8 cols)
    const int lrow = tid >> 1;
    const int lc4  = (tid & 1) * 4;

    const float* Ap = A + (size_t)(m0 + lrow) * K + lc4;
    const float* Wp = W + (size_t)(n0 + lrow) * K + lc4;

    float acc[8][8];
#pragma unroll
    for (int i = 0; i < 8; i++)
#pragma unroll
        for (int j = 0; j < 8; j++) acc[i][j] = 0.f;

    for (int k0 = 0; k0 < K; k0 += BK) {
        float4 av = *(const float4*)(Ap + k0);
        float4 wv = *(const float4*)(Wp + k0);
        As[lc4 + 0][lrow] = av.x;
        As[lc4 + 1][lrow] = av.y;
        As[lc4 + 2][lrow] = av.z;
        As[lc4 + 3][lrow] = av.w;
        Bs[lc4 + 0][lrow] = wv.x;
        Bs[lc4 + 1][lrow] = wv.y;
        Bs[lc4 + 2][lrow] = wv.z;
        Bs[lc4 + 3][lrow] = wv.w;
        __syncthreads();

#pragma unroll
        for (int kk = 0; kk < BK; kk++) {
            float a[8], b[8];
            *(float4*)&a[0] = *(const float4*)&As[kk][ty * 8];
            *(float4*)&a[4] = *(const float4*)&As[kk][ty * 8 + 4];
            *(float4*)&b[0] = *(const float4*)&Bs[kk][tx * 8];
            *(float4*)&b[4] = *(const float4*)&Bs[kk][tx * 8 + 4];
#pragma unroll
            for (int i = 0; i < 8; i++)
#pragma unroll
                for (int j = 0; j < 8; j++)
                    acc[i][j] = fmaf(a[i], b[j], acc[i][j]);
        }
        __syncthreads();
    }

#pragma unroll
    for (int i = 0; i < 8; i++) {
        const int m = m0 + ty * 8 + i;
        const int b = m >> 10;          // / NL
        const int l = m & (NL - 1);
#pragma unroll
        for (int j = 0; j < 8; j++) {
            const int n = n0 + tx * 8 + j;
            float v = acc[i][j] + bias[n];
            if (MODE == 0) {
                if (n < ND) {
                    const int h = n >> 6, hd = n & 63;
                    g_Q[(((size_t)b * NH + h) * NL + l) * NHD + hd] = v * NSCALE;
                } else if (n < 2 * ND) {
                    const int nn = n - ND;
                    const int h = nn >> 6, hd = nn & 63;
                    g_K[(((size_t)b * NH + h) * NL + l) * NHD + hd] = v;
                } else {
                    const int nn = n - 2 * ND;
                    const int h = nn >> 6, hd = nn & 63;
                    g_V[(((size_t)b * NH + h) * NL + l) * NHD + hd] = v;
                }
            } else {
                out[(size_t)m * ND + n] = v;
            }
        }
    }
}

// ---------------------------------------------------------------------------
// Fused attention: per block = one (b,h) x 64 query rows; loops over 16 key
// tiles of 64. Online softmax (flash style), bias streamed straight from
// gmem into fragments. Thread map: 16x16, each thread owns a 4x4 fragment.
// smem: Qt [d][r], KP [d][c] (reused as P^T [c][r]), Vs [c][d]; all with a
// 4-float-group XOR swizzle so the transposed stores don't serialize.
// ---------------------------------------------------------------------------
__device__ __forceinline__ int swz(int row, int col)
{
    return row * 64 + ((((col >> 2) ^ (row & 15)) << 2) | (col & 3));
}

__global__ __launch_bounds__(256)
void attn_kernel(const float* __restrict__ bias)
{
    __shared__ float Qt[64 * 64];
    __shared__ float KP[64 * 64];
    __shared__ float Vs[64 * 64];

    const int tid = threadIdx.x;
    const int tx = tid & 15;   // key-col / out-dim group
    const int ty = tid >> 4;   // query-row group
    const int bh = blockIdx.y;           // 0..47
    const int b = bh / NH;
    const int h = bh - b * NH;
    const int q0 = blockIdx.x * 64;

    const float* Qg = g_Q + (size_t)(bh * NL + q0) * NHD;
    const float* Kg = g_K + (size_t)bh * NL * NHD;
    const float* Vg = g_V + (size_t)bh * NL * NHD;
    const float* Bg = bias + ((size_t)bh * NL + q0) * NL;

    // Load Q tile transposed into Qt[d][r]
#pragma unroll
    for (int u = 0; u < 4; u++) {
        const int f = tid + 256 * u;     // 0..1023 float4s
        const int r = f >> 4;
        const int d = (f & 15) * 4;
        float4 v = *(const float4*)(Qg + r * NHD + d);
        Qt[swz(d + 0, r)] = v.x;
        Qt[swz(d + 1, r)] = v.y;
        Qt[swz(d + 2, r)] = v.z;
        Qt[swz(d + 3, r)] = v.w;
    }

    float mrow[4], lrow[4], o[4][4];
#pragma unroll
    for (int i = 0; i < 4; i++) {
        mrow[i] = -1e30f;
        lrow[i] = 0.f;
#pragma unroll
        for (int j = 0; j < 4; j++) o[i][j] = 0.f;
    }

    for (int kt = 0; kt < 16; kt++) {
        const int kb = kt * 64;
        __syncthreads();   // previous tile's KP/Vs reads complete

        // Load K tile transposed (Kt[d][c]) and V tile natural (Vs[c][d])
#pragma unroll
        for (int u = 0; u < 4; u++) {
            const int f = tid + 256 * u;
            const int c = f >> 4;
            const int d4 = f & 15;
            const int d = d4 * 4;
            float4 kv = *(const float4*)(Kg + (size_t)(kb + c) * NHD + d);
            KP[swz(d + 0, c)] = kv.x;
            KP[swz(d + 1, c)] = kv.y;
            KP[swz(d + 2, c)] = kv.z;
            KP[swz(d + 3, c)] = kv.w;
            float4 vv = *(const float4*)(Vg + (size_t)(kb + c) * NHD + d);
            *(float4*)&Vs[c * 64 + ((d4 ^ (c & 15)) << 2)] = vv;
        }
        __syncthreads();

        // S = Q K^T + bias  (fragment 4x4 per thread)
        float s[4][4];
#pragma unroll
        for (int i = 0; i < 4; i++) {
            float4 bv = *(const float4*)(Bg + (size_t)(ty * 4 + i) * NL + kb + tx * 4);
            s[i][0] = bv.x; s[i][1] = bv.y; s[i][2] = bv.z; s[i][3] = bv.w;
        }
#pragma unroll 8
        for (int d = 0; d < 64; d++) {
            float4 qv = *(const float4*)&Qt[d * 64 + ((ty ^ (d & 15)) << 2)];
            float4 kv = *(const float4*)&KP[d * 64 + ((tx ^ (d & 15)) << 2)];
            const float qa[4] = {qv.x, qv.y, qv.z, qv.w};
            const float ka[4] = {kv.x, kv.y, kv.z, kv.w};
#pragma unroll
            for (int i = 0; i < 4; i++)
#pragma unroll
                for (int j = 0; j < 4; j++)
                    s[i][j] = fmaf(qa[i], ka[j], s[i][j]);
        }

        // Online softmax update; row spread over 16 lanes (tx) of same warp half
#pragma unroll
        for (int i = 0; i < 4; i++) {
            float mx = fmaxf(fmaxf(s[i][0], s[i][1]), fmaxf(s[i][2], s[i][3]));
#pragma unroll
            for (int off = 8; off > 0; off >>= 1)
                mx = fmaxf(mx, __shfl_xor_sync(0xffffffffu, mx, off));
            const float mnew = fmaxf(mrow[i], mx);
            const float corr = __expf(mrow[i] - mnew);
            mrow[i] = mnew;
            lrow[i] *= corr;
#pragma unroll
            for (int j = 0; j < 4; j++) o[i][j] *= corr;
            float ls = 0.f;
#pragma unroll
            for (int j = 0; j < 4; j++) {
                const float p = __expf(s[i][j] - mnew);
                s[i][j] = p;
                ls += p;
            }
            lrow[i] += ls;   // partial (this thread's 4 cols); reduced at end
        }

        __syncthreads();   // everyone done reading KP as K^T
        // Store P^T into KP: row = key col, col = query row
#pragma unroll
        for (int j = 0; j < 4; j++)
#pragma unroll
            for (int i = 0; i < 4; i++)
                KP[swz(tx * 4 + j, ty * 4 + i)] = s[i][j];
        __syncthreads();

        // O += P V
#pragma unroll 8
        for (int c = 0; c < 64; c++) {
            float4 pv = *(const float4*)&KP[c * 64 + ((ty ^ (c & 15)) << 2)];
            float4 vv = *(const float4*)&Vs[c * 64 + ((tx ^ (c & 15)) << 2)];
            const float pa[4] = {pv.x, pv.y, pv.z, pv.w};
            const float va[4] = {vv.x, vv.y, vv.z, vv.w};
#pragma unroll
            for (int i = 0; i < 4; i++)
#pragma unroll
                for (int j = 0; j < 4; j++)
                    o[i][j] = fmaf(pa[i], va[j], o[i][j]);
        }
    }

    // Finalize: reduce row sums across 16 lanes, normalize, write O[b,l,h*64+d]
#pragma unroll
    for (int i = 0; i < 4; i++) {
        float l = lrow[i];
#pragma unroll
        for (int off = 8; off > 0; off >>= 1)
            l += __shfl_xor_sync(0xffffffffu, l, off);
        const float inv = 1.0f / l;
        const int q = q0 + ty * 4 + i;
        float4 res = make_float4(o[i][0] * inv, o[i][1] * inv,
                                 o[i][2] * inv, o[i][3] * inv);
        *(float4*)(g_O + (size_t)(b * NL + q) * ND + h * NHD + tx * 4) = res;
    }
}

// ---------------------------------------------------------------------------
extern "C" void kernel_launch(void* const* d_in, const int* in_sizes, int n_in,
                              void* d_out, int out_size)
{
    (void)in_sizes; (void)n_in; (void)out_size;
    const float* x     = (const float*)d_in[0];
    const float* ab    = (const float*)d_in[1];
    const float* w_in  = (const float*)d_in[2];
    const float* b_in  = (const float*)d_in[3];
    const float* w_out = (const float*)d_in[4];
    const float* b_out = (const float*)d_in[5];
    float* out = (float*)d_out;

    // 1) QKV projection: [4096,768] x [2304,768]^T -> scatter Q(scaled)/K/V
    sgemm_kernel<0><<<dim3(2304 / 128, 4096 / 128), 256>>>(x, w_in, b_in, nullptr);
    // 2) Fused biased attention + softmax -> g_O [B,L,D]
    attn_kernel<<<dim3(NL / 64, NB * NH), 256>>>(ab);
    // 3) Output projection: [4096,768] x [768,768]^T + bias -> d_out
    sgemm_kernel<1><<<dim3(768 / 128, 4096 / 128), 256>>>(nullptr, w_out, b_out, out);
}

// round 4
// speedup vs baseline: 2.5922x; 2.5922x over previous
#include <cuda_runtime.h>
#include <cuda_bf16.h>

#define NB 4
#define NL 1024
#define ND 768
#define NH 12
#define NHD 64
#define NSCALE 0.125f

typedef __nv_bfloat16 bf16;

// global scratch (allocation-free rule)
__device__ bf16 g_Xhi[NB*NL*ND], g_Xlo[NB*NL*ND];
__device__ bf16 g_Wihi[3*ND*ND], g_Wilo[3*ND*ND];
__device__ bf16 g_Wohi[ND*ND],   g_Wolo[ND*ND];
__device__ bf16 g_Qhi[NB*NH*NL*NHD], g_Qlo[NB*NH*NL*NHD];
__device__ bf16 g_Khi[NB*NH*NL*NHD], g_Klo[NB*NH*NL*NHD];
__device__ bf16 g_Vhi[NB*NH*NL*NHD], g_Vlo[NB*NH*NL*NHD];
__device__ bf16 g_Ohi[NB*NL*ND], g_Olo[NB*NL*ND];

__device__ __forceinline__ unsigned smu(const void* p){ return (unsigned)__cvta_generic_to_shared(p); }

__device__ __forceinline__ void ldsm4(unsigned r[4], unsigned a){
    asm volatile("ldmatrix.sync.aligned.m8n8.x4.shared.b16 {%0,%1,%2,%3},[%4];"
                 :"=r"(r[0]),"=r"(r[1]),"=r"(r[2]),"=r"(r[3]):"r"(a));
}
__device__ __forceinline__ void ldsm4t(unsigned r[4], unsigned a){
    asm volatile("ldmatrix.sync.aligned.m8n8.x4.trans.shared.b16 {%0,%1,%2,%3},[%4];"
                 :"=r"(r[0]),"=r"(r[1]),"=r"(r[2]),"=r"(r[3]):"r"(a));
}
__device__ __forceinline__ void mma16816(float c[4], const unsigned a[4], unsigned b0, unsigned b1){
    asm volatile("mma.sync.aligned.m16n8k16.row.col.f32.bf16.bf16.f32 "
                 "{%0,%1,%2,%3},{%4,%5,%6,%7},{%8,%9},{%0,%1,%2,%3};"
                 :"+f"(c[0]),"+f"(c[1]),"+f"(c[2]),"+f"(c[3])
                 :"r"(a[0]),"r"(a[1]),"r"(a[2]),"r"(a[3]),"r"(b0),"r"(b1));
}
// pack two fp32 -> bf16x2 hi and lo (x = hi + lo)
__device__ __forceinline__ void split2(float x0, float x1, unsigned& hi, unsigned& lo){
    bf16 h0 = __float2bfloat16(x0), h1 = __float2bfloat16(x1);
    bf16 l0 = __float2bfloat16(x0 - __bfloat162float(h0));
    bf16 l1 = __float2bfloat16(x1 - __bfloat162float(h1));
    hi = (unsigned)__bfloat16_as_ushort(h0) | ((unsigned)__bfloat16_as_ushort(h1) << 16);
    lo = (unsigned)__bfloat16_as_ushort(l0) | ((unsigned)__bfloat16_as_ushort(l1) << 16);
}

__global__ void split_inputs(const float* __restrict__ x, const float* __restrict__ wi,
                             const float* __restrict__ wo){
    const int st = gridDim.x * blockDim.x, i0 = blockIdx.x * blockDim.x + threadIdx.x;
    unsigned h0,l0,h1,l1;
    for (int i = i0; i < (NB*NL*ND)/4; i += st){
        float4 v = ((const float4*)x)[i];
        split2(v.x,v.y,h0,l0); split2(v.z,v.w,h1,l1);
        ((uint2*)g_Xhi)[i] = make_uint2(h0,h1); ((uint2*)g_Xlo)[i] = make_uint2(l0,l1);
    }
    for (int i = i0; i < (3*ND*ND)/4; i += st){
        float4 v = ((const float4*)wi)[i];
        split2(v.x,v.y,h0,l0); split2(v.z,v.w,h1,l1);
        ((uint2*)g_Wihi)[i] = make_uint2(h0,h1); ((uint2*)g_Wilo)[i] = make_uint2(l0,l1);
    }
    for (int i = i0; i < (ND*ND)/4; i += st){
        float4 v = ((const float4*)wo)[i];
        split2(v.x,v.y,h0,l0); split2(v.z,v.w,h1,l1);
        ((uint2*)g_Wohi)[i] = make_uint2(h0,h1); ((uint2*)g_Wolo)[i] = make_uint2(l0,l1);
    }
}

__device__ __forceinline__ void scatter_qkv(int m, int n, float v){
    const int b = m >> 10, l = m & 1023;
    bf16 *hi, *lo; int nn;
    if (n < ND)        { hi=g_Qhi; lo=g_Qlo; nn=n;      v *= NSCALE; }
    else if (n < 2*ND) { hi=g_Khi; lo=g_Klo; nn=n-ND;   }
    else               { hi=g_Vhi; lo=g_Vlo; nn=n-2*ND; }
    const size_t idx = (((size_t)b*NH + (nn>>6))*NL + l)*NHD + (nn&63);
    bf16 hv = __float2bfloat16(v);
    hi[idx] = hv; lo[idx] = __float2bfloat16(v - __bfloat162float(hv));
}

// GEMM C[m,n] = sum_k A[m,k] W[n,k] + bias[n], K=768, tiles 128x128x16.
// MODE 0: A=X, W=Wi -> scatter split QKV.  MODE 1: A=O, W=Wo -> fp32 out.
template <int MODE>
__global__ __launch_bounds__(256)
void gemm_mma(const float* __restrict__ bias, float* __restrict__ out){
    constexpr int K = 768;
    __shared__ __align__(16) bf16 sA[2][2][128*24];  // rows padded to 48B
    __shared__ __align__(16) bf16 sB[2][2][128*24];

    const bf16* Ahi = (MODE==0) ? g_Xhi : g_Ohi;
    const bf16* Alo = (MODE==0) ? g_Xlo : g_Olo;
    const bf16* Bhi = (MODE==0) ? g_Wihi : g_Wohi;
    const bf16* Blo = (MODE==0) ? g_Wilo : g_Wolo;

    const int tid = threadIdx.x, lane = tid & 31;
    const int g = lane >> 2, t = lane & 3;
    const int wid = tid >> 5, wm = wid >> 2, wn = wid & 3;   // 2x4 warps
    const int m0 = blockIdx.y * 128, n0 = blockIdx.x * 128;

    const int lr = tid >> 1, lh = tid & 1;
    const bf16* ApH = Ahi + (size_t)(m0+lr)*K + lh*8;
    const bf16* ApL = Alo + (size_t)(m0+lr)*K + lh*8;
    const bf16* BpH = Bhi + (size_t)(n0+lr)*K + lh*8;
    const bf16* BpL = Blo + (size_t)(n0+lr)*K + lh*8;
    const size_t so = (size_t)lr*48 + lh*16;

    float c[4][4][4];
#pragma unroll
    for (int i=0;i<4;i++)
#pragma unroll
        for (int j=0;j<4;j++){ c[i][j][0]=c[i][j][1]=c[i][j][2]=c[i][j][3]=0.f; }

    *(uint4*)((char*)sA[0][0]+so) = *(const uint4*)ApH;
    *(uint4*)((char*)sA[0][1]+so) = *(const uint4*)ApL;
    *(uint4*)((char*)sB[0][0]+so) = *(const uint4*)BpH;
    *(uint4*)((char*)sB[0][1]+so) = *(const uint4*)BpL;
    __syncthreads();

    uint4 pah, pal, pbh, pbl;
#pragma unroll 1
    for (int kt = 0; kt < 48; kt++){
        const int cur = kt & 1;
        if (kt < 47){
            const int ko = (kt+1)*16;
            pah = *(const uint4*)(ApH+ko); pal = *(const uint4*)(ApL+ko);
            pbh = *(const uint4*)(BpH+ko); pbl = *(const uint4*)(BpL+ko);
        }
        unsigned ah[4][4], al[4][4], bh[2][4], bl[2][4];
#pragma unroll
        for (int im=0; im<4; im++){
            const unsigned off = (wm*64 + im*16 + (lane&15))*48 + (lane>>4)*16;
            ldsm4(ah[im], smu((char*)sA[cur][0]+off));
            ldsm4(al[im], smu((char*)sA[cur][1]+off));
        }
#pragma unroll
        for (int jg=0; jg<2; jg++){
            const unsigned off = (wn*32 + jg*16 + (lane&15))*48 + (lane>>4)*16;
            ldsm4(bh[jg], smu((char*)sB[cur][0]+off));
            ldsm4(bl[jg], smu((char*)sB[cur][1]+off));
        }
#pragma unroll
        for (int im=0; im<4; im++)
#pragma unroll
            for (int jn=0; jn<4; jn++){
                const int jg = jn>>1, od = jn&1;
                const unsigned b0h = bh[jg][od], b1h = bh[jg][od+2];
                const unsigned b0l = bl[jg][od], b1l = bl[jg][od+2];
                mma16816(c[im][jn], ah[im], b0h, b1h);
                mma16816(c[im][jn], al[im], b0h, b1h);
                mma16816(c[im][jn], ah[im], b0l, b1l);
            }
        if (kt < 47){
            const int nx = cur ^ 1;
            *(uint4*)((char*)sA[nx][0]+so) = pah;
            *(uint4*)((char*)sA[nx][1]+so) = pal;
            *(uint4*)((char*)sB[nx][0]+so) = pbh;
            *(uint4*)((char*)sB[nx][1]+so) = pbl;
        }
        __syncthreads();
    }

#pragma unroll
    for (int im=0; im<4; im++)
#pragma unroll
        for (int jn=0; jn<4; jn++){
            const int n = n0 + wn*32 + jn*8 + 2*t;
            const float bv0 = bias[n], bv1 = bias[n+1];
#pragma unroll
            for (int hf=0; hf<2; hf++){
                const int m = m0 + wm*64 + im*16 + g + hf*8;
                const float v0 = c[im][jn][hf*2+0] + bv0;
                const float v1 = c[im][jn][hf*2+1] + bv1;
                if (MODE == 0){ scatter_qkv(m, n, v0); scatter_qkv(m, n+1, v1); }
                else          { *(float2*)(out + (size_t)m*ND + n) = make_float2(v0, v1); }
            }
        }
}

// copy 64x64 bf16 tile (hi+lo) gmem->smem with chunk^=(row&7) swizzle
__device__ __forceinline__ void copy_tile(bf16* dh, bf16* dl, const bf16* sh,
                                          const bf16* sl, int tid){
#pragma unroll
    for (int u=0; u<4; u++){
        const int it = tid + 128*u, row = it>>3, ck = it&7, ch = ck ^ (row&7);
        *(uint4*)((char*)dh + row*128 + ch*16) = *(const uint4*)((const char*)sh + row*128 + ck*16);
        *(uint4*)((char*)dl + row*128 + ch*16) = *(const uint4*)((const char*)sl + row*128 + ck*16);
    }
}

// FA2 attention: block = 64 queries x (b,h), 128 threads. S-frag == P A-frag.
__global__ __launch_bounds__(128)
void attn_mma(const float* __restrict__ bias){
    __shared__ __align__(16) bf16 sQ[2][64*64], sK[2][64*64], sV[2][64*64];

    const int tid = threadIdx.x, w = tid>>5, lane = tid&31;
    const int g = lane>>2, t = lane&3;
    const int bh = blockIdx.y, q0 = blockIdx.x*64;
    const int b = bh/NH, hh = bh - b*NH;
    const size_t head = (size_t)bh*NL*NHD;

    copy_tile(sQ[0], sQ[1], g_Qhi + head + (size_t)q0*NHD, g_Qlo + head + (size_t)q0*NHD, tid);

    const float* Bg = bias + ((size_t)bh*NL + q0)*NL;
    float o[8][4];
#pragma unroll
    for (int jd=0;jd<8;jd++){ o[jd][0]=o[jd][1]=o[jd][2]=o[jd][3]=0.f; }
    float mrow[2] = {-1e30f,-1e30f}, lrow[2] = {0.f,0.f};

#pragma unroll 1
    for (int kt = 0; kt < 16; kt++){
        __syncthreads();
        copy_tile(sK[0], sK[1], g_Khi + head + (size_t)kt*64*NHD, g_Klo + head + (size_t)kt*64*NHD, tid);
        copy_tile(sV[0], sV[1], g_Vhi + head + (size_t)kt*64*NHD, g_Vlo + head + (size_t)kt*64*NHD, tid);
        __syncthreads();

        // S = bias + Q K^T
        float s[8][4];
        {
            const float* bp0 = Bg + (size_t)(w*16+g)*NL + kt*64 + 2*t;
            const float* bp1 = bp0 + 8*NL;
#pragma unroll
            for (int jn=0; jn<8; jn++){
                float2 v0 = *(const float2*)(bp0 + jn*8);
                float2 v1 = *(const float2*)(bp1 + jn*8);
                s[jn][0]=v0.x; s[jn][1]=v0.y; s[jn][2]=v1.x; s[jn][3]=v1.y;
            }
        }
#pragma unroll
        for (int kk=0; kk<4; kk++){
            unsigned qh[4], ql[4], kh[4][4], kl[4][4];
            {
                const int row = w*16 + (lane&15);
                const int ch = (kk*2 + (lane>>4)) ^ (row&7);
                ldsm4(qh, smu((char*)sQ[0] + row*128 + ch*16));
                ldsm4(ql, smu((char*)sQ[1] + row*128 + ch*16));
            }
#pragma unroll
            for (int jg=0; jg<4; jg++){
                const int row = jg*16 + (lane&15);
                const int ch = (kk*2 + (lane>>4)) ^ (row&7);
                ldsm4(kh[jg], smu((char*)sK[0] + row*128 + ch*16));
                ldsm4(kl[jg], smu((char*)sK[1] + row*128 + ch*16));
            }
#pragma unroll
            for (int jn=0; jn<8; jn++){
                const int jg = jn>>1, od = jn&1;
                mma16816(s[jn], qh, kh[jg][od], kh[jg][od+2]);
                mma16816(s[jn], ql, kh[jg][od], kh[jg][od+2]);
                mma16816(s[jn], qh, kl[jg][od], kl[jg][od+2]);
            }
        }
        // online softmax (rows g, g+8; cols spread over t-quartet)
#pragma unroll
        for (int r=0; r<2; r++){
            float mx = -1e30f;
#pragma unroll
            for (int jn=0; jn<8; jn++) mx = fmaxf(mx, fmaxf(s[jn][2*r], s[jn][2*r+1]));
            mx = fmaxf(mx, __shfl_xor_sync(0xffffffffu, mx, 1));
            mx = fmaxf(mx, __shfl_xor_sync(0xffffffffu, mx, 2));
            const float mnew = fmaxf(mrow[r], mx);
            const float corr = __expf(mrow[r] - mnew);
            mrow[r] = mnew;
            float ls = 0.f;
#pragma unroll
            for (int jn=0; jn<8; jn++){
                const float p0 = __expf(s[jn][2*r] - mnew);
                const float p1 = __expf(s[jn][2*r+1] - mnew);
                s[jn][2*r] = p0; s[jn][2*r+1] = p1; ls += p0 + p1;
            }
            lrow[r] = lrow[r]*corr + ls;
#pragma unroll
            for (int jd=0; jd<8; jd++){ o[jd][2*r] *= corr; o[jd][2*r+1] *= corr; }
        }
        // O += P V   (P packed from s in regs; V via ldmatrix.trans)
#pragma unroll
        for (int kc=0; kc<4; kc++){
            unsigned aph[4], apl[4];
            split2(s[2*kc][0],   s[2*kc][1],   aph[0], apl[0]);
            split2(s[2*kc][2],   s[2*kc][3],   aph[1], apl[1]);
            split2(s[2*kc+1][0], s[2*kc+1][1], aph[2], apl[2]);
            split2(s[2*kc+1][2], s[2*kc+1][3], aph[3], apl[3]);
#pragma unroll
            for (int dch=0; dch<4; dch++){
                unsigned vh[4], vl[4];
                const int row = kc*16 + (lane&15);
                const int ch = (dch*2 + (lane>>4)) ^ (row&7);
                ldsm4t(vh, smu((char*)sV[0] + row*128 + ch*16));
                ldsm4t(vl, smu((char*)sV[1] + row*128 + ch*16));
#pragma unroll
                for (int od=0; od<2; od++){
                    const int jd = dch*2 + od;
                    mma16816(o[jd], aph, vh[od*2], vh[od*2+1]);
                    mma16816(o[jd], apl, vh[od*2], vh[od*2+1]);
                    mma16816(o[jd], aph, vl[od*2], vl[od*2+1]);
                }
            }
        }
    }

    // finalize: reduce row-sum over t, normalize, write split O
    float inv[2];
#pragma unroll
    for (int r=0; r<2; r++){
        float l = lrow[r];
        l += __shfl_xor_sync(0xffffffffu, l, 1);
        l += __shfl_xor_sync(0xffffffffu, l, 2);
        inv[r] = 1.0f / l;
    }
#pragma unroll
    for (int jd=0; jd<8; jd++)
#pragma unroll
        for (int r=0; r<2; r++){
            const int q = q0 + w*16 + g + r*8;
            const int col = hh*64 + jd*8 + 2*t;
            const size_t idx = ((size_t)b*NL + q)*ND + col;
            unsigned hi, lo;
            split2(o[jd][2*r]*inv[r], o[jd][2*r+1]*inv[r], hi, lo);
            *(unsigned*)(g_Ohi + idx) = hi;
            *(unsigned*)(g_Olo + idx) = lo;
        }
}

extern "C" void kernel_launch(void* const* d_in, const int* in_sizes, int n_in,
                              void* d_out, int out_size){
    (void)in_sizes; (void)n_in; (void)out_size;
    const float* x     = (const float*)d_in[0];
    const float* ab    = (const float*)d_in[1];
    const float* w_in  = (const float*)d_in[2];
    const float* b_in  = (const float*)d_in[3];
    const float* w_out = (const float*)d_in[4];
    const float* b_out = (const float*)d_in[5];
    float* out = (float*)d_out;

    split_inputs<<<512, 256>>>(x, w_in, w_out);
    gemm_mma<0><<<dim3(18, 32), 256>>>(b_in, nullptr);
    attn_mma<<<dim3(16, 48), 128>>>(ab);
    gemm_mma<1><<<dim3(6, 32), 256>>>(b_out, out);
}

// round 5
// speedup vs baseline: 2.6086x; 1.0063x over previous
#include <cuda_runtime.h>
#include <cuda_bf16.h>

#define NB 4
#define NL 1024
#define ND 768
#define NH 12
#define NHD 64
#define NSCALE 0.125f

typedef __nv_bfloat16 bf16;

// global scratch (allocation-free rule)
__device__ bf16 g_Xhi[NB*NL*ND], g_Xlo[NB*NL*ND];
__device__ bf16 g_Wihi[3*ND*ND], g_Wilo[3*ND*ND];
__device__ bf16 g_Wohi[ND*ND],   g_Wolo[ND*ND];
__device__ bf16 g_Qhi[NB*NH*NL*NHD], g_Qlo[NB*NH*NL*NHD];
__device__ bf16 g_Khi[NB*NH*NL*NHD], g_Klo[NB*NH*NL*NHD];
__device__ bf16 g_Vhi[NB*NH*NL*NHD], g_Vlo[NB*NH*NL*NHD];
__device__ bf16 g_Ohi[NB*NL*ND], g_Olo[NB*NL*ND];

__device__ __forceinline__ unsigned smu(const void* p){ return (unsigned)__cvta_generic_to_shared(p); }

__device__ __forceinline__ void ldsm4(unsigned r[4], unsigned a){
    asm volatile("ldmatrix.sync.aligned.m8n8.x4.shared.b16 {%0,%1,%2,%3},[%4];"
                 :"=r"(r[0]),"=r"(r[1]),"=r"(r[2]),"=r"(r[3]):"r"(a));
}
__device__ __forceinline__ void ldsm4t(unsigned r[4], unsigned a){
    asm volatile("ldmatrix.sync.aligned.m8n8.x4.trans.shared.b16 {%0,%1,%2,%3},[%4];"
                 :"=r"(r[0]),"=r"(r[1]),"=r"(r[2]),"=r"(r[3]):"r"(a));
}
__device__ __forceinline__ void mma16816(float c[4], const unsigned a[4], unsigned b0, unsigned b1){
    asm volatile("mma.sync.aligned.m16n8k16.row.col.f32.bf16.bf16.f32 "
                 "{%0,%1,%2,%3},{%4,%5,%6,%7},{%8,%9},{%0,%1,%2,%3};"
                 :"+f"(c[0]),"+f"(c[1]),"+f"(c[2]),"+f"(c[3])
                 :"r"(a[0]),"r"(a[1]),"r"(a[2]),"r"(a[3]),"r"(b0),"r"(b1));
}
__device__ __forceinline__ void split2(float x0, float x1, unsigned& hi, unsigned& lo){
    bf16 h0 = __float2bfloat16(x0), h1 = __float2bfloat16(x1);
    bf16 l0 = __float2bfloat16(x0 - __bfloat162float(h0));
    bf16 l1 = __float2bfloat16(x1 - __bfloat162float(h1));
    hi = (unsigned)__bfloat16_as_ushort(h0) | ((unsigned)__bfloat16_as_ushort(h1) << 16);
    lo = (unsigned)__bfloat16_as_ushort(l0) | ((unsigned)__bfloat16_as_ushort(l1) << 16);
}
__device__ __forceinline__ void cpa16(unsigned d, const void* s){
    asm volatile("cp.async.cg.shared.global [%0],[%1],16;"::"r"(d),"l"(s));
}
__device__ __forceinline__ void cp_commit(){ asm volatile("cp.async.commit_group;"); }
template<int N> __device__ __forceinline__ void cp_wait(){
    asm volatile("cp.async.wait_group %0;"::"n"(N));
}

__global__ void split_inputs(const float* __restrict__ x, const float* __restrict__ wi,
                             const float* __restrict__ wo){
    const int st = gridDim.x * blockDim.x, i0 = blockIdx.x * blockDim.x + threadIdx.x;
    unsigned h0,l0,h1,l1;
    for (int i = i0; i < (NB*NL*ND)/4; i += st){
        float4 v = ((const float4*)x)[i];
        split2(v.x,v.y,h0,l0); split2(v.z,v.w,h1,l1);
        ((uint2*)g_Xhi)[i] = make_uint2(h0,h1); ((uint2*)g_Xlo)[i] = make_uint2(l0,l1);
    }
    for (int i = i0; i < (3*ND*ND)/4; i += st){
        float4 v = ((const float4*)wi)[i];
        split2(v.x,v.y,h0,l0); split2(v.z,v.w,h1,l1);
        ((uint2*)g_Wihi)[i] = make_uint2(h0,h1); ((uint2*)g_Wilo)[i] = make_uint2(l0,l1);
    }
    for (int i = i0; i < (ND*ND)/4; i += st){
        float4 v = ((const float4*)wo)[i];
        split2(v.x,v.y,h0,l0); split2(v.z,v.w,h1,l1);
        ((uint2*)g_Wohi)[i] = make_uint2(h0,h1); ((uint2*)g_Wolo)[i] = make_uint2(l0,l1);
    }
}

__device__ __forceinline__ void scatter_qkv(int m, int n, float v){
    const int b = m >> 10, l = m & 1023;
    bf16 *hi, *lo; int nn;
    if (n < ND)        { hi=g_Qhi; lo=g_Qlo; nn=n;      v *= NSCALE; }
    else if (n < 2*ND) { hi=g_Khi; lo=g_Klo; nn=n-ND;   }
    else               { hi=g_Vhi; lo=g_Vlo; nn=n-2*ND; }
    const size_t idx = (((size_t)b*NH + (nn>>6))*NL + l)*NHD + (nn&63);
    bf16 hv = __float2bfloat16(v);
    hi[idx] = hv; lo[idx] = __float2bfloat16(v - __bfloat162float(hv));
}

// GEMM C[m,n] = sum_k A[m,k] W[n,k] + bias[n]; 128x128x16 tiles, cp.async 3-stage.
// dyn smem: 3 stages x (Ahi|Alo|Bhi|Blo), each 128 rows x 48B = 6144B -> 73728B.
template <int MODE>
__global__ __launch_bounds__(256, 2)
void gemm_mma(const float* __restrict__ bias, float* __restrict__ out){
    constexpr int K = 768, NKT = 48;
    extern __shared__ char dsm[];

    const bf16* Ahi = (MODE==0) ? g_Xhi : g_Ohi;
    const bf16* Alo = (MODE==0) ? g_Xlo : g_Olo;
    const bf16* Bhi = (MODE==0) ? g_Wihi : g_Wohi;
    const bf16* Blo = (MODE==0) ? g_Wilo : g_Wolo;

    const int tid = threadIdx.x, lane = tid & 31;
    const int g = lane >> 2, t = lane & 3;
    const int wid = tid >> 5, wm = wid >> 2, wn = wid & 3;
    const int m0 = blockIdx.y * 128, n0 = blockIdx.x * 128;
    const int lr = tid >> 1, lh = tid & 1;
    const bf16* ApH = Ahi + (size_t)(m0+lr)*K + lh*8;
    const bf16* ApL = Alo + (size_t)(m0+lr)*K + lh*8;
    const bf16* BpH = Bhi + (size_t)(n0+lr)*K + lh*8;
    const bf16* BpL = Blo + (size_t)(n0+lr)*K + lh*8;
    const unsigned so = lr*48 + lh*16;

    float c[4][4][4];
#pragma unroll
    for (int i=0;i<4;i++)
#pragma unroll
        for (int j=0;j<4;j++){ c[i][j][0]=c[i][j][1]=c[i][j][2]=c[i][j][3]=0.f; }

#define G_ISSUE(S,KT) do{ char* st_ = dsm + (S)*24576; const int ko_ = (KT)*16;   \
    cpa16(smu(st_)+so,       ApH+ko_); cpa16(smu(st_+6144)+so,  ApL+ko_);         \
    cpa16(smu(st_+12288)+so, BpH+ko_); cpa16(smu(st_+18432)+so, BpL+ko_);         \
    cp_commit(); }while(0)

    G_ISSUE(0,0); G_ISSUE(1,1);

#pragma unroll 1
    for (int kt = 0; kt < NKT; kt++){
        cp_wait<1>();
        __syncthreads();
        if (kt+2 < NKT) G_ISSUE((kt+2)%3, kt+2); else cp_commit();

        char* st = dsm + (kt%3)*24576;
        unsigned ah[4][4], al[4][4], bh[2][4], bl[2][4];
#pragma unroll
        for (int im=0; im<4; im++){
            const unsigned off = (wm*64 + im*16 + (lane&15))*48 + (lane>>4)*16;
            ldsm4(ah[im], smu(st)+off);
            ldsm4(al[im], smu(st+6144)+off);
        }
#pragma unroll
        for (int jg=0; jg<2; jg++){
            const unsigned off = (wn*32 + jg*16 + (lane&15))*48 + (lane>>4)*16;
            ldsm4(bh[jg], smu(st+12288)+off);
            ldsm4(bl[jg], smu(st+18432)+off);
        }
#pragma unroll
        for (int im=0; im<4; im++)
#pragma unroll
            for (int jn=0; jn<4; jn++){
                const int jg = jn>>1, od = jn&1;
                mma16816(c[im][jn], ah[im], bh[jg][od], bh[jg][od+2]);
                mma16816(c[im][jn], al[im], bh[jg][od], bh[jg][od+2]);
                mma16816(c[im][jn], ah[im], bl[jg][od], bl[jg][od+2]);
            }
    }

#pragma unroll
    for (int im=0; im<4; im++)
#pragma unroll
        for (int jn=0; jn<4; jn++){
            const int n = n0 + wn*32 + jn*8 + 2*t;
            const float bv0 = bias[n], bv1 = bias[n+1];
#pragma unroll
            for (int hf=0; hf<2; hf++){
                const int m = m0 + wm*64 + im*16 + g + hf*8;
                const float v0 = c[im][jn][hf*2+0] + bv0;
                const float v1 = c[im][jn][hf*2+1] + bv1;
                if (MODE == 0){ scatter_qkv(m, n, v0); scatter_qkv(m, n+1, v1); }
                else          { *(float2*)(out + (size_t)m*ND + n) = make_float2(v0, v1); }
            }
        }
}

// cp.async a 64x64 bf16 tile with chunk^=(row&7) swizzle (128 threads x 4 x 16B)
__device__ __forceinline__ void tissue(char* dst, const bf16* src, int tid){
#pragma unroll
    for (int u=0; u<4; u++){
        const int it = tid + 128*u, row = it>>3, ck = it&7, ch = ck ^ (row&7);
        cpa16(smu(dst + row*128 + ch*16), (const char*)src + row*128 + ck*16);
    }
}

// FA2 attention: 64 queries x (b,h) per block, 128 threads.
// Q fragments register-resident; K/V double-buffered via cp.async.
// dyn smem: K[2 stages][hi/lo] 4x8KB + V same = 65536B.
__global__ __launch_bounds__(128, 3)
void attn_mma(const float* __restrict__ bias){
    extern __shared__ char dsm[];
#define KBUF(s,cc) (dsm + ((s)*2+(cc))*8192)
#define VBUF(s,cc) (dsm + 32768 + ((s)*2+(cc))*8192)

    const int tid = threadIdx.x, w = tid>>5, lane = tid&31;
    const int g = lane>>2, t = lane&3;
    const int bh = blockIdx.y, q0 = blockIdx.x*64;
    const int b = bh/NH, hh = bh - b*NH;
    const size_t head = (size_t)bh*NL*NHD;

    // prologue: stage Q (into stage-1 K buffers) + kt=0 K/V
    tissue(KBUF(1,0), g_Qhi + head + (size_t)q0*NHD, tid);
    tissue(KBUF(1,1), g_Qlo + head + (size_t)q0*NHD, tid);
    tissue(KBUF(0,0), g_Khi + head, tid);
    tissue(KBUF(0,1), g_Klo + head, tid);
    tissue(VBUF(0,0), g_Vhi + head, tid);
    tissue(VBUF(0,1), g_Vlo + head, tid);
    cp_commit();
    cp_wait<0>();
    __syncthreads();

    unsigned qh[4][4], ql[4][4];
#pragma unroll
    for (int kk=0; kk<4; kk++){
        const int row = w*16 + (lane&15);
        const int ch = (kk*2 + (lane>>4)) ^ (row&7);
        ldsm4(qh[kk], smu(KBUF(1,0) + row*128 + ch*16));
        ldsm4(ql[kk], smu(KBUF(1,1) + row*128 + ch*16));
    }
    __syncthreads();   // Q frags read before kt=1 overwrites stage-1 buffers

    const float* Bg = bias + ((size_t)bh*NL + q0)*NL;
    float o[8][4];
#pragma unroll
    for (int jd=0;jd<8;jd++){ o[jd][0]=o[jd][1]=o[jd][2]=o[jd][3]=0.f; }
    float mrow[2] = {-1e30f,-1e30f}, lrow[2] = {0.f,0.f};

#pragma unroll 1
    for (int kt = 0; kt < 16; kt++){
        const int cur = kt & 1;
        if (kt+1 < 16){
            const int nx = cur ^ 1;
            const size_t off = head + (size_t)(kt+1)*64*NHD;
            tissue(KBUF(nx,0), g_Khi + off, tid);
            tissue(KBUF(nx,1), g_Klo + off, tid);
            tissue(VBUF(nx,0), g_Vhi + off, tid);
            tissue(VBUF(nx,1), g_Vlo + off, tid);
        }
        cp_commit();

        // S = bias + Q K^T
        float s[8][4];
        {
            const float* bp0 = Bg + (size_t)(w*16+g)*NL + kt*64 + 2*t;
            const float* bp1 = bp0 + 8*NL;
#pragma unroll
            for (int jn=0; jn<8; jn++){
                float2 v0 = *(const float2*)(bp0 + jn*8);
                float2 v1 = *(const float2*)(bp1 + jn*8);
                s[jn][0]=v0.x; s[jn][1]=v0.y; s[jn][2]=v1.x; s[jn][3]=v1.y;
            }
        }
#pragma unroll
        for (int kk=0; kk<4; kk++){
            unsigned kh[4][4], kl[4][4];
#pragma unroll
            for (int jg=0; jg<4; jg++){
                const int row = jg*16 + (lane&15);
                const int ch = (kk*2 + (lane>>4)) ^ (row&7);
                ldsm4(kh[jg], smu(KBUF(cur,0) + row*128 + ch*16));
                ldsm4(kl[jg], smu(KBUF(cur,1) + row*128 + ch*16));
            }
#pragma unroll
            for (int jn=0; jn<8; jn++){
                const int jg = jn>>1, od = jn&1;
                mma16816(s[jn], qh[kk], kh[jg][od], kh[jg][od+2]);
                mma16816(s[jn], ql[kk], kh[jg][od], kh[jg][od+2]);
                mma16816(s[jn], qh[kk], kl[jg][od], kl[jg][od+2]);
            }
        }
        // online softmax (rows g, g+8; cols spread over t-quartet)
#pragma unroll
        for (int r=0; r<2; r++){
            float mx = -1e30f;
#pragma unroll
            for (int jn=0; jn<8; jn++) mx = fmaxf(mx, fmaxf(s[jn][2*r], s[jn][2*r+1]));
            mx = fmaxf(mx, __shfl_xor_sync(0xffffffffu, mx, 1));
            mx = fmaxf(mx, __shfl_xor_sync(0xffffffffu, mx, 2));
            const float mnew = fmaxf(mrow[r], mx);
            const float corr = __expf(mrow[r] - mnew);
            mrow[r] = mnew;
            float ls = 0.f;
#pragma unroll
            for (int jn=0; jn<8; jn++){
                const float p0 = __expf(s[jn][2*r] - mnew);
                const float p1 = __expf(s[jn][2*r+1] - mnew);
                s[jn][2*r] = p0; s[jn][2*r+1] = p1; ls += p0 + p1;
            }
            lrow[r] = lrow[r]*corr + ls;
#pragma unroll
            for (int jd=0; jd<8; jd++){ o[jd][2*r] *= corr; o[jd][2*r+1] *= corr; }
        }
        // O += P V
#pragma unroll
        for (int kc=0; kc<4; kc++){
            unsigned aph[4], apl[4];
            split2(s[2*kc][0],   s[2*kc][1],   aph[0], apl[0]);
            split2(s[2*kc][2],   s[2*kc][3],   aph[1], apl[1]);
            split2(s[2*kc+1][0], s[2*kc+1][1], aph[2], apl[2]);
            split2(s[2*kc+1][2], s[2*kc+1][3], aph[3], apl[3]);
#pragma unroll
            for (int dch=0; dch<4; dch++){
                unsigned vh[4], vl[4];
                const int row = kc*16 + (lane&15);
                const int ch = (dch*2 + (lane>>4)) ^ (row&7);
                ldsm4t(vh, smu(VBUF(cur,0) + row*128 + ch*16));
                ldsm4t(vl, smu(VBUF(cur,1) + row*128 + ch*16));
#pragma unroll
                for (int od=0; od<2; od++){
                    const int jd = dch*2 + od;
                    mma16816(o[jd], aph, vh[od*2], vh[od*2+1]);
                    mma16816(o[jd], apl, vh[od*2], vh[od*2+1]);
                    mma16816(o[jd], aph, vl[od*2], vl[od*2+1]);
                }
            }
        }
        cp_wait<0>();
        __syncthreads();
    }

    float inv[2];
#pragma unroll
    for (int r=0; r<2; r++){
        float l = lrow[r];
        l += __shfl_xor_sync(0xffffffffu, l, 1);
        l += __shfl_xor_sync(0xffffffffu, l, 2);
        inv[r] = 1.0f / l;
    }
#pragma unroll
    for (int jd=0; jd<8; jd++)
#pragma unroll
        for (int r=0; r<2; r++){
            const int q = q0 + w*16 + g + r*8;
            const int col = hh*64 + jd*8 + 2*t;
            const size_t idx = ((size_t)b*NL + q)*ND + col;
            unsigned hi, lo;
            split2(o[jd][2*r]*inv[r], o[jd][2*r+1]*inv[r], hi, lo);
            *(unsigned*)(g_Ohi + idx) = hi;
            *(unsigned*)(g_Olo + idx) = lo;
        }
}

extern "C" void kernel_launch(void* const* d_in, const int* in_sizes, int n_in,
                              void* d_out, int out_size){
    (void)in_sizes; (void)n_in; (void)out_size;
    const float* x     = (const float*)d_in[0];
    const float* ab    = (const float*)d_in[1];
    const float* w_in  = (const float*)d_in[2];
    const float* b_in  = (const float*)d_in[3];
    const float* w_out = (const float*)d_in[4];
    const float* b_out = (const float*)d_in[5];
    float* out = (float*)d_out;

    cudaFuncSetAttribute(gemm_mma<0>, cudaFuncAttributeMaxDynamicSharedMemorySize, 73728);
    cudaFuncSetAttribute(gemm_mma<1>, cudaFuncAttributeMaxDynamicSharedMemorySize, 73728);
    cudaFuncSetAttribute(attn_mma,    cudaFuncAttributeMaxDynamicSharedMemorySize, 65536);

    split_inputs<<<512, 256>>>(x, w_in, w_out);
    gemm_mma<0><<<dim3(18, 32), 256, 73728>>>(b_in, nullptr);
    attn_mma<<<dim3(16, 48), 128, 65536>>>(ab);
    gemm_mma<1><<<dim3(6, 32), 256, 73728>>>(b_out, out);
}

// round 7
// speedup vs baseline: 2.7209x; 1.0430x over previous
#include <cuda_runtime.h>
#include <cuda_bf16.h>

#define NB 4
#define NL 1024
#define ND 768
#define NH 12
#define NHD 64
#define NSCALE 0.125f

typedef __nv_bfloat16 bf16;

// global scratch (allocation-free rule)
__device__ bf16 g_Xhi[NB*NL*ND], g_Xlo[NB*NL*ND];
__device__ bf16 g_Wihi[3*ND*ND], g_Wilo[3*ND*ND];
__device__ bf16 g_Wohi[ND*ND],   g_Wolo[ND*ND];
__device__ bf16 g_Qhi[NB*NH*NL*NHD], g_Qlo[NB*NH*NL*NHD];
__device__ bf16 g_Khi[NB*NH*NL*NHD], g_Klo[NB*NH*NL*NHD];
__device__ bf16 g_Vhi[NB*NH*NL*NHD], g_Vlo[NB*NH*NL*NHD];
__device__ bf16 g_Ohi[NB*NL*ND], g_Olo[NB*NL*ND];

__device__ __forceinline__ unsigned smu(const void* p){ return (unsigned)__cvta_generic_to_shared(p); }

__device__ __forceinline__ void ldsm4(unsigned r[4], unsigned a){
    asm volatile("ldmatrix.sync.aligned.m8n8.x4.shared.b16 {%0,%1,%2,%3},[%4];"
                 :"=r"(r[0]),"=r"(r[1]),"=r"(r[2]),"=r"(r[3]):"r"(a));
}
__device__ __forceinline__ void ldsm4t(unsigned r[4], unsigned a){
    asm volatile("ldmatrix.sync.aligned.m8n8.x4.trans.shared.b16 {%0,%1,%2,%3},[%4];"
                 :"=r"(r[0]),"=r"(r[1]),"=r"(r[2]),"=r"(r[3]):"r"(a));
}
__device__ __forceinline__ void mma16816(float c[4], const unsigned a[4], unsigned b0, unsigned b1){
    asm volatile("mma.sync.aligned.m16n8k16.row.col.f32.bf16.bf16.f32 "
                 "{%0,%1,%2,%3},{%4,%5,%6,%7},{%8,%9},{%0,%1,%2,%3};"
                 :"+f"(c[0]),"+f"(c[1]),"+f"(c[2]),"+f"(c[3])
                 :"r"(a[0]),"r"(a[1]),"r"(a[2]),"r"(a[3]),"r"(b0),"r"(b1));
}
__device__ __forceinline__ void split2(float x0, float x1, unsigned& hi, unsigned& lo){
    bf16 h0 = __float2bfloat16(x0), h1 = __float2bfloat16(x1);
    bf16 l0 = __float2bfloat16(x0 - __bfloat162float(h0));
    bf16 l1 = __float2bfloat16(x1 - __bfloat162float(h1));
    hi = (unsigned)__bfloat16_as_ushort(h0) | ((unsigned)__bfloat16_as_ushort(h1) << 16);
    lo = (unsigned)__bfloat16_as_ushort(l0) | ((unsigned)__bfloat16_as_ushort(l1) << 16);
}
__device__ __forceinline__ void cpa16(unsigned d, const void* s){
    asm volatile("cp.async.cg.shared.global [%0],[%1],16;"::"r"(d),"l"(s));
}
__device__ __forceinline__ void cp_commit(){ asm volatile("cp.async.commit_group;"); }
template<int N> __device__ __forceinline__ void cp_wait(){
    asm volatile("cp.async.wait_group %0;"::"n"(N));
}

__global__ void split_inputs(const float* __restrict__ x, const float* __restrict__ wi,
                             const float* __restrict__ wo){
    const int st = gridDim.x * blockDim.x, i0 = blockIdx.x * blockDim.x + threadIdx.x;
    unsigned h0,l0,h1,l1;
    for (int i = i0; i < (NB*NL*ND)/4; i += st){
        float4 v = ((const float4*)x)[i];
        split2(v.x,v.y,h0,l0); split2(v.z,v.w,h1,l1);
        ((uint2*)g_Xhi)[i] = make_uint2(h0,h1); ((uint2*)g_Xlo)[i] = make_uint2(l0,l1);
    }
    for (int i = i0; i < (3*ND*ND)/4; i += st){
        float4 v = ((const float4*)wi)[i];
        split2(v.x,v.y,h0,l0); split2(v.z,v.w,h1,l1);
        ((uint2*)g_Wihi)[i] = make_uint2(h0,h1); ((uint2*)g_Wilo)[i] = make_uint2(l0,l1);
    }
    for (int i = i0; i < (ND*ND)/4; i += st){
        float4 v = ((const float4*)wo)[i];
        split2(v.x,v.y,h0,l0); split2(v.z,v.w,h1,l1);
        ((uint2*)g_Wohi)[i] = make_uint2(h0,h1); ((uint2*)g_Wolo)[i] = make_uint2(l0,l1);
    }
}

__device__ __forceinline__ void scatter_qkv(int m, int n, float v){
    const int b = m >> 10, l = m & 1023;
    bf16 *hi, *lo; int nn;
    if (n < ND)        { hi=g_Qhi; lo=g_Qlo; nn=n;      v *= NSCALE; }
    else if (n < 2*ND) { hi=g_Khi; lo=g_Klo; nn=n-ND;   }
    else               { hi=g_Vhi; lo=g_Vlo; nn=n-2*ND; }
    const size_t idx = (((size_t)b*NH + (nn>>6))*NL + l)*NHD + (nn&63);
    bf16 hv = __float2bfloat16(v);
    hi[idx] = hv; lo[idx] = __float2bfloat16(v - __bfloat162float(hv));
}

// GEMM C[m,n] = sum_k A[m,k] W[n,k] + bias[n]; 128x128x16 tiles.
// 4-stage cp.async pipeline (wait_group 2), LDSM-before-fill ordering,
// three-pass MMA issue.  dyn smem: 4 x 24576 = 98304 B.
template <int MODE>
__global__ __launch_bounds__(256, 2)
void gemm_mma(const float* __restrict__ bias, float* __restrict__ out){
    constexpr int K = 768, NKT = 48;
    extern __shared__ char dsm[];

    const bf16* Ahi = (MODE==0) ? g_Xhi : g_Ohi;
    const bf16* Alo = (MODE==0) ? g_Xlo : g_Olo;
    const bf16* Bhi = (MODE==0) ? g_Wihi : g_Wohi;
    const bf16* Blo = (MODE==0) ? g_Wilo : g_Wolo;

    const int tid = threadIdx.x, lane = tid & 31;
    const int g = lane >> 2, t = lane & 3;
    const int wid = tid >> 5, wm = wid >> 2, wn = wid & 3;   // 2x4 warps
    const int m0 = blockIdx.y * 128, n0 = blockIdx.x * 128;
    const int lr = tid >> 1, lh = tid & 1;
    const bf16* ApH = Ahi + (size_t)(m0+lr)*K + lh*8;
    const bf16* ApL = Alo + (size_t)(m0+lr)*K + lh*8;
    const bf16* BpH = Bhi + (size_t)(n0+lr)*K + lh*8;
    const bf16* BpL = Blo + (size_t)(n0+lr)*K + lh*8;
    const unsigned so = lr*48 + lh*16;

    float c[4][4][4];
#pragma unroll
    for (int i=0;i<4;i++)
#pragma unroll
        for (int j=0;j<4;j++){ c[i][j][0]=c[i][j][1]=c[i][j][2]=c[i][j][3]=0.f; }

#define G_ISSUE(S,KT) do{ char* st_ = dsm + (S)*24576; const int ko_ = (KT)*16;   \
    cpa16(smu(st_)+so,       ApH+ko_); cpa16(smu(st_+6144)+so,  ApL+ko_);         \
    cpa16(smu(st_+12288)+so, BpH+ko_); cpa16(smu(st_+18432)+so, BpL+ko_);         \
    cp_commit(); }while(0)

    G_ISSUE(0,0); G_ISSUE(1,1); G_ISSUE(2,2);

    const unsigned aoff = (wm*64 + (lane&15))*48 + (lane>>4)*16;
    const unsigned boff = (wn*32 + (lane&15))*48 + (lane>>4)*16;

#pragma unroll 1
    for (int kt = 0; kt < NKT; kt++){
        cp_wait<2>();
        __syncthreads();
        char* st = dsm + (kt & 3)*24576;

        // fragments first (LDS pipe), then queue next-stage LDGs behind them
        unsigned ah[4][4], al[4][4], bh[2][4], bl[2][4];
#pragma unroll
        for (int im=0; im<4; im++){
            ldsm4(ah[im], smu(st)      + aoff + im*16*48);
            ldsm4(al[im], smu(st+6144) + aoff + im*16*48);
        }
#pragma unroll
        for (int jg=0; jg<2; jg++){
            ldsm4(bh[jg], smu(st+12288) + boff + jg*16*48);
            ldsm4(bl[jg], smu(st+18432) + boff + jg*16*48);
        }

        if (kt + 3 < NKT) G_ISSUE((kt+3) & 3, kt+3); else cp_commit();

        // pass 1: hi*hi  (16 independent accumulator chains)
#pragma unroll
        for (int im=0; im<4; im++)
#pragma unroll
            for (int jn=0; jn<4; jn++){
                const int jg = jn>>1, od = jn&1;
                mma16816(c[im][jn], ah[im], bh[jg][od], bh[jg][od+2]);
            }
        // pass 2: lo*hi
#pragma unroll
        for (int im=0; im<4; im++)
#pragma unroll
            for (int jn=0; jn<4; jn++){
                const int jg = jn>>1, od = jn&1;
                mma16816(c[im][jn], al[im], bh[jg][od], bh[jg][od+2]);
            }
        // pass 3: hi*lo
#pragma unroll
        for (int im=0; im<4; im++)
#pragma unroll
            for (int jn=0; jn<4; jn++){
                const int jg = jn>>1, od = jn&1;
                mma16816(c[im][jn], ah[im], bl[jg][od], bl[jg][od+2]);
            }
    }

#pragma unroll
    for (int im=0; im<4; im++)
#pragma unroll
        for (int jn=0; jn<4; jn++){
            const int n = n0 + wn*32 + jn*8 + 2*t;
            const float bv0 = bias[n], bv1 = bias[n+1];
#pragma unroll
            for (int hf=0; hf<2; hf++){
                const int m = m0 + wm*64 + im*16 + g + hf*8;
                const float v0 = c[im][jn][hf*2+0] + bv0;
                const float v1 = c[im][jn][hf*2+1] + bv1;
                if (MODE == 0){ scatter_qkv(m, n, v0); scatter_qkv(m, n+1, v1); }
                else          { *(float2*)(out + (size_t)m*ND + n) = make_float2(v0, v1); }
            }
        }
}

// cp.async a 64x64 bf16 tile with chunk^=(row&7) swizzle (128 threads x 4 x 16B)
__device__ __forceinline__ void tissue(char* dst, const bf16* src, int tid){
#pragma unroll
    for (int u=0; u<4; u++){
        const int it = tid + 128*u, row = it>>3, ck = it&7, ch = ck ^ (row&7);
        cpa16(smu(dst + row*128 + ch*16), (const char*)src + row*128 + ck*16);
    }
}

// FA2 attention (mma.sync): 64 queries x (b,h) per block, 128 threads.
// Q fragments register-resident; K/V double-buffered via cp.async.
__global__ __launch_bounds__(128, 3)
void attn_mma(const float* __restrict__ bias){
    extern __shared__ char dsm[];
#define KBUF(s,cc) (dsm + ((s)*2+(cc))*8192)
#define VBUF(s,cc) (dsm + 32768 + ((s)*2+(cc))*8192)

    const int tid = threadIdx.x, w = tid>>5, lane = tid&31;
    const int g = lane>>2, t = lane&3;
    const int bh = blockIdx.y, q0 = blockIdx.x*64;
    const int b = bh/NH, hh = bh - b*NH;
    const size_t head = (size_t)bh*NL*NHD;

    tissue(KBUF(1,0), g_Qhi + head + (size_t)q0*NHD, tid);
    tissue(KBUF(1,1), g_Qlo + head + (size_t)q0*NHD, tid);
    tissue(KBUF(0,0), g_Khi + head, tid);
    tissue(KBUF(0,1), g_Klo + head, tid);
    tissue(VBUF(0,0), g_Vhi + head, tid);
    tissue(VBUF(0,1), g_Vlo + head, tid);
    cp_commit();
    cp_wait<0>();
    __syncthreads();

    unsigned qh[4][4], ql[4][4];
#pragma unroll
    for (int kk=0; kk<4; kk++){
        const int row = w*16 + (lane&15);
        const int ch = (kk*2 + (lane>>4)) ^ (row&7);
        ldsm4(qh[kk], smu(KBUF(1,0) + row*128 + ch*16));
        ldsm4(ql[kk], smu(KBUF(1,1) + row*128 + ch*16));
    }
    __syncthreads();

    const float* Bg = bias + ((size_t)bh*NL + q0)*NL;
    float o[8][4];
#pragma unroll
    for (int jd=0;jd<8;jd++){ o[jd][0]=o[jd][1]=o[jd][2]=o[jd][3]=0.f; }
    float mrow[2] = {-1e30f,-1e30f}, lrow[2] = {0.f,0.f};

#pragma unroll 1
    for (int kt = 0; kt < 16; kt++){
        const int cur = kt & 1;
        if (kt+1 < 16){
            const int nx = cur ^ 1;
            const size_t off = head + (size_t)(kt+1)*64*NHD;
            tissue(KBUF(nx,0), g_Khi + off, tid);
            tissue(KBUF(nx,1), g_Klo + off, tid);
            tissue(VBUF(nx,0), g_Vhi + off, tid);
            tissue(VBUF(nx,1), g_Vlo + off, tid);
        }
        cp_commit();

        float s[8][4];
        {
            const float* bp0 = Bg + (size_t)(w*16+g)*NL + kt*64 + 2*t;
            const float* bp1 = bp0 + 8*NL;
#pragma unroll
            for (int jn=0; jn<8; jn++){
                float2 v0 = *(const float2*)(bp0 + jn*8);
                float2 v1 = *(const float2*)(bp1 + jn*8);
                s[jn][0]=v0.x; s[jn][1]=v0.y; s[jn][2]=v1.x; s[jn][3]=v1.y;
            }
        }
#pragma unroll
        for (int kk=0; kk<4; kk++){
            unsigned kh[4][4], kl[4][4];
#pragma unroll
            for (int jg=0; jg<4; jg++){
                const int row = jg*16 + (lane&15);
                const int ch = (kk*2 + (lane>>4)) ^ (row&7);
                ldsm4(kh[jg], smu(KBUF(cur,0) + row*128 + ch*16));
                ldsm4(kl[jg], smu(KBUF(cur,1) + row*128 + ch*16));
            }
#pragma unroll
            for (int jn=0; jn<8; jn++){
                const int jg = jn>>1, od = jn&1;
                mma16816(s[jn], qh[kk], kh[jg][od], kh[jg][od+2]);
                mma16816(s[jn], ql[kk], kh[jg][od], kh[jg][od+2]);
                mma16816(s[jn], qh[kk], kl[jg][od], kl[jg][od+2]);
            }
        }
#pragma unroll
        for (int r=0; r<2; r++){
            float mx = -1e30f;
#pragma unroll
            for (int jn=0; jn<8; jn++) mx = fmaxf(mx, fmaxf(s[jn][2*r], s[jn][2*r+1]));
            mx = fmaxf(mx, __shfl_xor_sync(0xffffffffu, mx, 1));
            mx = fmaxf(mx, __shfl_xor_sync(0xffffffffu, mx, 2));
            const float mnew = fmaxf(mrow[r], mx);
            const float corr = __expf(mrow[r] - mnew);
            mrow[r] = mnew;
            float ls = 0.f;
#pragma unroll
            for (int jn=0; jn<8; jn++){
                const float p0 = __expf(s[jn][2*r] - mnew);
                const float p1 = __expf(s[jn][2*r+1] - mnew);
                s[jn][2*r] = p0; s[jn][2*r+1] = p1; ls += p0 + p1;
            }
            lrow[r] = lrow[r]*corr + ls;
#pragma unroll
            for (int jd=0; jd<8; jd++){ o[jd][2*r] *= corr; o[jd][2*r+1] *= corr; }
        }
#pragma unroll
        for (int kc=0; kc<4; kc++){
            unsigned aph[4], apl[4];
            split2(s[2*kc][0],   s[2*kc][1],   aph[0], apl[0]);
            split2(s[2*kc][2],   s[2*kc][3],   aph[1], apl[1]);
            split2(s[2*kc+1][0], s[2*kc+1][1], aph[2], apl[2]);
            split2(s[2*kc+1][2], s[2*kc+1][3], aph[3], apl[3]);
#pragma unroll
            for (int dch=0; dch<4; dch++){
                unsigned vh[4], vl[4];
                const int row = kc*16 + (lane&15);
                const int ch = (dch*2 + (lane>>4)) ^ (row&7);
                ldsm4t(vh, smu(VBUF(cur,0) + row*128 + ch*16));
                ldsm4t(vl, smu(VBUF(cur,1) + row*128 + ch*16));
#pragma unroll
                for (int od=0; od<2; od++){
                    const int jd = dch*2 + od;
                    mma16816(o[jd], aph, vh[od*2], vh[od*2+1]);
                    mma16816(o[jd], apl, vh[od*2], vh[od*2+1]);
                    mma16816(o[jd], aph, vl[od*2], vl[od*2+1]);
                }
            }
        }
        cp_wait<0>();
        __syncthreads();
    }

    float inv[2];
#pragma unroll
    for (int r=0; r<2; r++){
        float l = lrow[r];
        l += __shfl_xor_sync(0xffffffffu, l, 1);
        l += __shfl_xor_sync(0xffffffffu, l, 2);
        inv[r] = 1.0f / l;
    }
#pragma unroll
    for (int jd=0; jd<8; jd++)
#pragma unroll
        for (int r=0; r<2; r++){
            const int q = q0 + w*16 + g + r*8;
            const int col = hh*64 + jd*8 + 2*t;
            const size_t idx = ((size_t)b*NL + q)*ND + col;
            unsigned hi, lo;
            split2(o[jd][2*r]*inv[r], o[jd][2*r+1]*inv[r], hi, lo);
            *(unsigned*)(g_Ohi + idx) = hi;
            *(unsigned*)(g_Olo + idx) = lo;
        }
}

extern "C" void kernel_launch(void* const* d_in, const int* in_sizes, int n_in,
                              void* d_out, int out_size){
    (void)in_sizes; (void)n_in; (void)out_size;
    const float* x     = (const float*)d_in[0];
    const float* ab    = (const float*)d_in[1];
    const float* w_in  = (const float*)d_in[2];
    const float* b_in  = (const float*)d_in[3];
    const float* w_out = (const float*)d_in[4];
    const float* b_out = (const float*)d_in[5];
    float* out = (float*)d_out;

    cudaFuncSetAttribute(gemm_mma<0>, cudaFuncAttributeMaxDynamicSharedMemorySize, 98304);
    cudaFuncSetAttribute(gemm_mma<1>, cudaFuncAttributeMaxDynamicSharedMemorySize, 98304);
    cudaFuncSetAttribute(attn_mma,    cudaFuncAttributeMaxDynamicSharedMemorySize, 65536);

    split_inputs<<<512, 256>>>(x, w_in, w_out);
    gemm_mma<0><<<dim3(18, 32), 256, 98304>>>(b_in, nullptr);
    attn_mma<<<dim3(16, 48), 128, 65536>>>(ab);
    gemm_mma<1><<<dim3(6, 32), 256, 98304>>>(b_out, out);
}